// round 4
// baseline (speedup 1.0000x reference)
#include <cuda_runtime.h>
#include <cstdint>

// SAME-padded stride-1 3x3 conv, NHWC fp32.
// Hybrid implicit GEMM: warps 0-15 tf32 mma.sync on 256 pixels,
// warps 16-19 FFMA on 64 more pixels, shared cp.async smem pipeline.
// x: [32,56,56,128], w: [3,3,128,256], b: [256] -> out: [32,56,56,256]

#define CB    32
#define CH    56
#define CW    56
#define CCIN  128
#define CCOUT 256
#define NPIX  (CB * CH * CW)      // 100352
#define NCHUNKS 36                // 9 taps * 4 cin-chunks of 32

#define BM_MMA 256
#define BM     320                // 256 mma + 64 ffma pixels
#define BN     128
#define BK     32
#define NTHREADS 640              // 16 mma warps + 4 ffma warps
#define STAGES 3

// smem strides in words (padded, conflict-free for mma fragment loads)
#define A_ROW 36                  // 32 k + 4 pad
#define B_ROW 132                 // 128 n + 4 pad
#define A_STAGE_W (BM * A_ROW)    // 11520 words (46080 B)
#define B_STAGE_W (BK * B_ROW)    // 4224 words  (16896 B)
#define SMEM_BYTES (STAGES * (A_STAGE_W + B_STAGE_W) * 4)   // 188928

// ---------------- helpers ----------------
__device__ __forceinline__ uint32_t smem_u32(const void* p) {
    uint32_t a;
    asm("{ .reg .u64 t; cvta.to.shared.u64 t, %1; cvt.u32.u64 %0, t; }"
        : "=r"(a) : "l"(p));
    return a;
}

__device__ __forceinline__ void cp16(uint32_t dst, const void* src, uint32_t srcsz) {
    asm volatile("cp.async.cg.shared.global [%0], [%1], 16, %2;"
                 :: "r"(dst), "l"(src), "r"(srcsz) : "memory");
}
#define CP_COMMIT() asm volatile("cp.async.commit_group;" ::: "memory")
#define CP_WAIT1()  asm volatile("cp.async.wait_group 1;" ::: "memory")

__device__ __forceinline__ void mma_tf32(float c[4], const uint32_t a[4],
                                         const uint32_t b[2]) {
    asm volatile(
        "mma.sync.aligned.m16n8k8.row.col.f32.tf32.tf32.f32 "
        "{%0,%1,%2,%3}, {%4,%5,%6,%7}, {%8,%9}, {%0,%1,%2,%3};"
        : "+f"(c[0]), "+f"(c[1]), "+f"(c[2]), "+f"(c[3])
        : "r"(a[0]), "r"(a[1]), "r"(a[2]), "r"(a[3]),
          "r"(b[0]), "r"(b[1]));
}

// fp32 -> tf32 with round-to-nearest (applied in-register on MMA fragments)
__device__ __forceinline__ uint32_t rna_u(float v) {
    uint32_t r;
    asm("cvt.rna.tf32.f32 %0, %1;" : "=r"(r) : "f"(v));
    return r;
}

// ---------------- kernel ----------------
__global__ __launch_bounds__(NTHREADS, 1)
void conv_hybrid(const float* __restrict__ x, const float* __restrict__ w,
                 const float* __restrict__ bias, float* __restrict__ out)
{
    extern __shared__ float smem[];
    const uint32_t sm_a = smem_u32(smem);
    const uint32_t sm_b = sm_a + STAGES * A_STAGE_W * 4;

    const int tid  = threadIdx.x;
    const int wid  = tid >> 5;
    const int lane = tid & 31;
    const int bn = blockIdx.x;     // 0..1
    const int bm = blockIdx.y;     // 0..313

    // unified accumulators: mma warps view as acc[4][4][4], ffma as facc[8][8]
    float regs[64];
    #pragma unroll
    for (int r = 0; r < 64; ++r) regs[r] = 0.0f;

    const int s7 = tid & 7;        // A loader: 16B segment within 128B chunk

    // ---------------- load issuer (all 640 threads) ----------------
    auto load_chunk = [&](int i, int stage) {
        const int tap = i >> 2, csub = i & 3;
        const int dh = tap / 3 - 1, dw = tap % 3 - 1;
        const uint32_t a_st = sm_a + stage * A_STAGE_W * 4;
        const uint32_t b_st = sm_b + stage * B_STAGE_W * 4;
        #pragma unroll
        for (int q = 0; q < 4; ++q) {
            const int row = (tid >> 3) + q * 80;       // 0..319
            const int pix = bm * BM + row;
            const bool pvq = (pix < NPIX);
            const int pc = pvq ? pix : 0;
            const int n  = pc / (CH * CW);
            const int hw = pc % (CH * CW);
            const int h2 = hw / CW + dh;
            const int w2 = hw % CW + dw;
            const bool ok = pvq && ((unsigned)h2 < CH) && ((unsigned)w2 < CW);
            const uint32_t off = ok
                ? ((uint32_t)n * (CH * CW * CCIN) + (uint32_t)(h2 * CW + w2) * CCIN
                   + csub * 32 + s7 * 4)
                : 0u;
            const uint32_t dst = a_st + (uint32_t)row * (A_ROW * 4) + s7 * 16;
            cp16(dst, x + off, ok ? 16u : 0u);
        }
        if (tid < 512) {
            #pragma unroll
            for (int q = 0; q < 2; ++q) {
                const int row = (tid >> 5) + q * 16;   // 0..31
                const float* src = w + ((size_t)(tap * 128 + csub * 32 + row) * CCOUT
                                        + bn * BN) + (tid & 31) * 4;
                cp16(b_st + (uint32_t)row * (B_ROW * 4) + (tid & 31) * 16, src, 16u);
            }
        }
        CP_COMMIT();
    };

    load_chunk(0, 0);
    load_chunk(1, 1);

    const int lr = lane >> 2, lc = lane & 3;       // mma fragment coords
    const int warp_m = wid >> 2, warp_n = wid & 3; // mma warp grid (wid<16)
    const int ftid = tid - 512;                    // ffma coords (wid>=16)
    const int fty = (ftid >> 4) & 7, ftx = ftid & 15;

    for (int i = 0; i < NCHUNKS; ++i) {
        CP_WAIT1();
        __syncthreads();

        if (i + 2 < NCHUNKS) load_chunk(i + 2, (i + 2) % STAGES);
        else CP_COMMIT();

        const int stage = i % STAGES;

        if (wid < 16) {
            // ---- tf32 mma path on pixels 0..255 of tile ----
            const float* As = smem + stage * A_STAGE_W + warp_m * 64 * A_ROW;
            const float* Bs = smem + STAGES * A_STAGE_W + stage * B_STAGE_W
                            + warp_n * 32;
            #pragma unroll
            for (int j = 0; j < 4; ++j) {
                const int k0 = j * 8 + lc;
                uint32_t a[4][4], b[4][2];
                #pragma unroll
                for (int t = 0; t < 4; ++t) {
                    const float* ap = As + (t * 16 + lr) * A_ROW + k0;
                    a[t][0] = rna_u(ap[0]);
                    a[t][1] = rna_u(ap[8 * A_ROW]);
                    a[t][2] = rna_u(ap[4]);
                    a[t][3] = rna_u(ap[8 * A_ROW + 4]);
                }
                #pragma unroll
                for (int u = 0; u < 4; ++u) {
                    const float* bp = Bs + k0 * B_ROW + u * 8 + lr;
                    b[u][0] = rna_u(bp[0]);
                    b[u][1] = rna_u(bp[4 * B_ROW]);
                }
                #pragma unroll
                for (int t = 0; t < 4; ++t)
                    #pragma unroll
                    for (int u = 0; u < 4; ++u)
                        mma_tf32(&regs[(t * 4 + u) * 4], a[t], b[u]);
            }
        } else {
            // ---- fp32 FFMA path on pixels 256..319 of tile ----
            const float* As = smem + stage * A_STAGE_W + (256 + fty * 8) * A_ROW;
            const float* Bs = smem + STAGES * A_STAGE_W + stage * B_STAGE_W
                            + ftx * 8;
            #pragma unroll 4
            for (int k = 0; k < BK; ++k) {
                const float4 p0 = *(const float4*)(Bs + k * B_ROW);
                const float4 p1 = *(const float4*)(Bs + k * B_ROW + 4);
                const float bb[8] = {p0.x, p0.y, p0.z, p0.w,
                                     p1.x, p1.y, p1.z, p1.w};
                #pragma unroll
                for (int ii = 0; ii < 8; ++ii) {
                    const float av = As[ii * A_ROW + k];
                    #pragma unroll
                    for (int jj = 0; jj < 8; ++jj)
                        regs[ii * 8 + jj] = fmaf(av, bb[jj], regs[ii * 8 + jj]);
                }
            }
        }
    }

    // ---------------- epilogue: bias + store ----------------
    if (wid < 16) {
        float bv0[4], bv1[4];
        #pragma unroll
        for (int u = 0; u < 4; ++u) {
            const int c = bn * BN + warp_n * 32 + u * 8 + lc * 2;
            bv0[u] = bias[c];
            bv1[u] = bias[c + 1];
        }
        #pragma unroll
        for (int t = 0; t < 4; ++t) {
            const int r0 = bm * BM + warp_m * 64 + t * 16 + lr;
            #pragma unroll
            for (int u = 0; u < 4; ++u) {
                const int c = bn * BN + warp_n * 32 + u * 8 + lc * 2;
                const float* a4 = &regs[(t * 4 + u) * 4];
                if (r0 < NPIX) {
                    float2 v0 = make_float2(a4[0] + bv0[u], a4[1] + bv1[u]);
                    *(float2*)(out + (size_t)r0 * CCOUT + c) = v0;
                }
                if (r0 + 8 < NPIX) {
                    float2 v1 = make_float2(a4[2] + bv0[u], a4[3] + bv1[u]);
                    *(float2*)(out + (size_t)(r0 + 8) * CCOUT + c) = v1;
                }
            }
        }
    } else {
        float bv[8];
        #pragma unroll
        for (int jj = 0; jj < 8; ++jj)
            bv[jj] = bias[bn * BN + ftx * 8 + jj];
        #pragma unroll
        for (int ii = 0; ii < 8; ++ii) {
            const int pix = bm * BM + 256 + fty * 8 + ii;
            if (pix < NPIX) {
                float* op = out + (size_t)pix * CCOUT + bn * BN + ftx * 8;
                float4 o0, o1;
                o0.x = regs[ii * 8 + 0] + bv[0];
                o0.y = regs[ii * 8 + 1] + bv[1];
                o0.z = regs[ii * 8 + 2] + bv[2];
                o0.w = regs[ii * 8 + 3] + bv[3];
                o1.x = regs[ii * 8 + 4] + bv[4];
                o1.y = regs[ii * 8 + 5] + bv[5];
                o1.z = regs[ii * 8 + 6] + bv[6];
                o1.w = regs[ii * 8 + 7] + bv[7];
                *(float4*)(op)     = o0;
                *(float4*)(op + 4) = o1;
            }
        }
    }
}

// ---------------- host launch ----------------
extern "C" void kernel_launch(void* const* d_in, const int* in_sizes, int n_in,
                              void* d_out, int out_size)
{
    const float* x    = (const float*)d_in[0];
    const float* w    = (const float*)d_in[1];
    const float* bias = (const float*)d_in[2];
    float* out = (float*)d_out;

    cudaFuncSetAttribute(conv_hybrid, cudaFuncAttributeMaxDynamicSharedMemorySize,
                         SMEM_BYTES);
    dim3 grid(CCOUT / BN, (NPIX + BM - 1) / BM);   // (2, 314)
    conv_hybrid<<<grid, NTHREADS, SMEM_BYTES>>>(x, w, bias, out);
}

// round 5
// speedup vs baseline: 2.7660x; 2.7660x over previous
#include <cuda_runtime.h>
#include <cstdint>

// SAME-padded stride-1 3x3 conv, NHWC fp32, tf32 mma.sync implicit GEMM.
// x: [32,56,56,128], w: [3,3,128,256], b: [256] -> out: [32,56,56,256]
// Pre-passes round to tf32(rne) and permute cin within 8-groups
// ([0,4,1,5,2,6,3,7]) so MMA fragments load as single LDS.64.

#define CB    32
#define CH    56
#define CW    56
#define CCIN  128
#define CCOUT 256
#define NPIX  (CB * CH * CW)      // 100352
#define KTOT  1152
#define NCHUNKS 36                // 9 taps * 4 cin-chunks of 32

#define BM 256
#define BN 128
#define BK 32
#define NTHREADS 512              // 16 warps, 4(M) x 4(N)
#define STAGES 3

// smem row strides in words: 32 data + 8 pad (stride mod 32 == 8 ->
// conflict-free float2 fragment loads per half-warp phase)
#define A_ROW 40
#define B_ROW 40
#define A_STAGE_W (BM * A_ROW)    // 10240 words (40960 B)
#define B_STAGE_W (BN * B_ROW)    // 5120 words  (20480 B)
#define SMEM_BYTES (STAGES * (A_STAGE_W + B_STAGE_W) * 4)   // 184320

// ---------------- scratch: tf32(rne)-rounded, cin-permuted copies ----------
__device__ __align__(1024) float g_x_t[NPIX * CCIN];    // [pix][cin']
__device__ __align__(1024) float g_w_t[CCOUT * KTOT];   // [cout][k'] transposed

// ---------------- helpers ----------------
__device__ __forceinline__ uint32_t smem_u32(const void* p) {
    uint32_t a;
    asm("{ .reg .u64 t; cvta.to.shared.u64 t, %1; cvt.u32.u64 %0, t; }"
        : "=r"(a) : "l"(p));
    return a;
}

__device__ __forceinline__ void cp16(uint32_t dst, const void* src, uint32_t srcsz) {
    asm volatile("cp.async.cg.shared.global [%0], [%1], 16, %2;"
                 :: "r"(dst), "l"(src), "r"(srcsz) : "memory");
}
#define CP_COMMIT() asm volatile("cp.async.commit_group;" ::: "memory")
#define CP_WAIT1()  asm volatile("cp.async.wait_group 1;" ::: "memory")

__device__ __forceinline__ void mma_tf32(float c[4], const uint32_t a[4],
                                         const uint32_t b[2]) {
    asm volatile(
        "mma.sync.aligned.m16n8k8.row.col.f32.tf32.tf32.f32 "
        "{%0,%1,%2,%3}, {%4,%5,%6,%7}, {%8,%9}, {%0,%1,%2,%3};"
        : "+f"(c[0]), "+f"(c[1]), "+f"(c[2]), "+f"(c[3])
        : "r"(a[0]), "r"(a[1]), "r"(a[2]), "r"(a[3]),
          "r"(b[0]), "r"(b[1]));
}

__device__ __forceinline__ float rna_tf32(float v) {
    uint32_t r;
    asm("cvt.rna.tf32.f32 %0, %1;" : "=r"(r) : "f"(v));
    return __uint_as_float(r);
}

// ---------------- pre-kernels ----------------
// x: per 8-group of cin, output order (c0,c4,c1,c5,c2,c6,c3,c7), tf32(rne).
__global__ void k_prep_x(const float* __restrict__ in, float* __restrict__ outp) {
    const int g = blockIdx.x * blockDim.x + threadIdx.x;   // 8-group index
    const float4* i4 = (const float4*)(in) + g * 2;
    float4 a = i4[0];   // c0..c3
    float4 b = i4[1];   // c4..c7
    float4 o0, o1;
    o0.x = rna_tf32(a.x); o0.y = rna_tf32(b.x);
    o0.z = rna_tf32(a.y); o0.w = rna_tf32(b.y);
    o1.x = rna_tf32(a.z); o1.y = rna_tf32(b.z);
    o1.z = rna_tf32(a.w); o1.w = rna_tf32(b.w);
    float4* o4 = (float4*)(outp) + g * 2;
    o4[0] = o0;
    o4[1] = o1;
}

// w[k][cout] -> w_t[cout][k'] with same within-8 permutation, tf32(rne).
__global__ void k_prep_w(const float* __restrict__ w, float* __restrict__ wt) {
    const int idx = blockIdx.x * blockDim.x + threadIdx.x;  // co-major over [co][kp]
    const int co = idx / KTOT;
    const int kp = idx % KTOT;
    const int g = kp >> 3, r = kp & 7;
    const int c = (r & 1) ? (4 + (r >> 1)) : (r >> 1);      // inverse permutation
    wt[idx] = rna_tf32(w[(size_t)(g * 8 + c) * CCOUT + co]);
}

// ---------------- main kernel ----------------
__global__ __launch_bounds__(NTHREADS, 1)
void conv_mma(const float* __restrict__ xt, const float* __restrict__ wt,
              const float* __restrict__ bias, float* __restrict__ out)
{
    extern __shared__ float smem[];
    const uint32_t sm_a = smem_u32(smem);
    const uint32_t sm_b = sm_a + STAGES * A_STAGE_W * 4;

    const int tid  = threadIdx.x;
    const int wid  = tid >> 5;
    const int lane = tid & 31;
    const int lr   = lane >> 2;    // 0..7
    const int lc   = lane & 3;     // 0..3
    const int bn = blockIdx.x;     // 0..1
    const int bm = blockIdx.y;     // 0..391

    // ---- A loader coords: 4 pixels per thread ----
    const int s7 = tid & 7;        // 16B segment within 128B cin-chunk
    int ah[4], aw[4];
    uint32_t abase[4];
    #pragma unroll
    for (int q = 0; q < 4; ++q) {
        int pix = bm * BM + (tid >> 3) + q * 64;
        int n   = pix / (CH * CW);
        int hw  = pix % (CH * CW);
        ah[q] = hw / CW;
        aw[q] = hw % CW;
        abase[q] = (uint32_t)n * (CH * CW * CCIN);
    }

    float acc[4][4][4];
    #pragma unroll
    for (int t = 0; t < 4; ++t)
        #pragma unroll
        for (int u = 0; u < 4; ++u)
            #pragma unroll
            for (int r = 0; r < 4; ++r)
                acc[t][u][r] = 0.0f;

    const int warp_m = wid >> 2;   // 0..3
    const int warp_n = wid & 3;    // 0..3

    // ---------------- load issuer ----------------
    auto load_chunk = [&](int i, int stage) {
        const int tap = i >> 2, csub = i & 3;
        const int dh = tap / 3 - 1, dw = tap % 3 - 1;
        const uint32_t a_st = sm_a + stage * A_STAGE_W * 4;
        const uint32_t b_st = sm_b + stage * B_STAGE_W * 4;
        #pragma unroll
        for (int q = 0; q < 4; ++q) {
            const int h2 = ah[q] + dh, w2 = aw[q] + dw;
            const bool ok = ((unsigned)h2 < CH) && ((unsigned)w2 < CW);
            const uint32_t off = ok
                ? (abase[q] + (uint32_t)(h2 * CW + w2) * CCIN + csub * 32 + s7 * 4)
                : 0u;
            const uint32_t dst = a_st
                + (uint32_t)((tid >> 3) + q * 64) * (A_ROW * 4) + s7 * 16;
            cp16(dst, xt + off, ok ? 16u : 0u);
        }
        // B: w_t[bn*128+row][tap*128 + csub*32 + seg*4], rows 0..127, 8 segs
        #pragma unroll
        for (int q = 0; q < 2; ++q) {
            const int f   = tid + q * 512;
            const int row = f >> 3;           // 0..127
            const int seg = f & 7;
            const float* src = wt + (size_t)(bn * BN + row) * KTOT
                             + tap * 128 + csub * 32 + seg * 4;
            cp16(b_st + (uint32_t)row * (B_ROW * 4) + seg * 16, src, 16u);
        }
        CP_COMMIT();
    };

    load_chunk(0, 0);
    load_chunk(1, 1);

    for (int i = 0; i < NCHUNKS; ++i) {
        CP_WAIT1();
        __syncthreads();

        if (i + 2 < NCHUNKS) load_chunk(i + 2, (i + 2) % STAGES);
        else CP_COMMIT();

        const int stage = i % STAGES;
        const float* As = smem + stage * A_STAGE_W + (warp_m * 64) * A_ROW;
        const float* Bs = smem + STAGES * A_STAGE_W + stage * B_STAGE_W
                        + (warp_n * 32) * B_ROW;

        #pragma unroll
        for (int j = 0; j < 4; ++j) {
            const int kc = j * 8 + lc * 2;   // permuted pair (orig lc, lc+4)
            uint32_t a[4][4], b[4][2];
            #pragma unroll
            for (int t = 0; t < 4; ++t) {
                const float2 lo = *(const float2*)(As + (t * 16 + lr) * A_ROW + kc);
                const float2 hi = *(const float2*)(As + (t * 16 + lr + 8) * A_ROW + kc);
                a[t][0] = __float_as_uint(lo.x);
                a[t][1] = __float_as_uint(hi.x);
                a[t][2] = __float_as_uint(lo.y);
                a[t][3] = __float_as_uint(hi.y);
            }
            #pragma unroll
            for (int u = 0; u < 4; ++u) {
                const float2 bb = *(const float2*)(Bs + (u * 8 + lr) * B_ROW + kc);
                b[u][0] = __float_as_uint(bb.x);
                b[u][1] = __float_as_uint(bb.y);
            }
            #pragma unroll
            for (int t = 0; t < 4; ++t)
                #pragma unroll
                for (int u = 0; u < 4; ++u)
                    mma_tf32(acc[t][u], a[t], b[u]);
        }
    }

    // ---------------- epilogue: bias + store ----------------
    float bv0[4], bv1[4];
    #pragma unroll
    for (int u = 0; u < 4; ++u) {
        const int c = bn * BN + warp_n * 32 + u * 8 + lc * 2;
        bv0[u] = bias[c];
        bv1[u] = bias[c + 1];
    }
    #pragma unroll
    for (int t = 0; t < 4; ++t) {
        const int r0 = bm * BM + warp_m * 64 + t * 16 + lr;
        #pragma unroll
        for (int u = 0; u < 4; ++u) {
            const int c = bn * BN + warp_n * 32 + u * 8 + lc * 2;
            float2 v0 = make_float2(acc[t][u][0] + bv0[u], acc[t][u][1] + bv1[u]);
            float2 v1 = make_float2(acc[t][u][2] + bv0[u], acc[t][u][3] + bv1[u]);
            *(float2*)(out + (size_t)r0 * CCOUT + c)       = v0;
            *(float2*)(out + (size_t)(r0 + 8) * CCOUT + c) = v1;
        }
    }
}

// ---------------- host launch ----------------
extern "C" void kernel_launch(void* const* d_in, const int* in_sizes, int n_in,
                              void* d_out, int out_size)
{
    const float* x    = (const float*)d_in[0];
    const float* w    = (const float*)d_in[1];
    const float* bias = (const float*)d_in[2];
    float* out = (float*)d_out;

    float *gx = nullptr, *gw = nullptr;
    cudaGetSymbolAddress((void**)&gx, g_x_t);
    cudaGetSymbolAddress((void**)&gw, g_w_t);

    // pre-passes: tf32(rne) + within-8 cin permutation (+ w transpose)
    k_prep_x<<<NPIX * CCIN / 8 / 256, 256>>>(x, gx);      // 6272 blocks
    k_prep_w<<<KTOT * CCOUT / 256, 256>>>(w, gw);         // 1152 blocks

    cudaFuncSetAttribute(conv_mma, cudaFuncAttributeMaxDynamicSharedMemorySize,
                         SMEM_BYTES);
    dim3 grid(CCOUT / BN, NPIX / BM);   // (2, 392)
    conv_mma<<<grid, NTHREADS, SMEM_BYTES>>>(gx, gw, bias, out);
}

// round 6
// speedup vs baseline: 2.7982x; 1.0116x over previous
#include <cuda_runtime.h>
#include <cstdint>

// SAME-padded stride-1 3x3 conv, NHWC fp32, tf32 mma.sync implicit GEMM.
// x: [32,56,56,128], w: [3,3,128,256], b: [256] -> out: [32,56,56,256]
// Round 6: 8 warps x (64x64) warp tiles -> 33% less fragment LDS traffic.

#define CB    32
#define CH    56
#define CW    56
#define CCIN  128
#define CCOUT 256
#define NPIX  (CB * CH * CW)      // 100352
#define KTOT  1152
#define NCHUNKS 36                // 9 taps * 4 cin-chunks of 32

#define BM 256
#define BN 128
#define BK 32
#define NTHREADS 256              // 8 warps, 4(M) x 2(N), 64x64 each
#define STAGES 3

// smem row strides in words: 32 data + 8 pad (conflict-free float2 loads)
#define A_ROW 40
#define B_ROW 40
#define A_STAGE_W (BM * A_ROW)    // 10240 words (40960 B)
#define B_STAGE_W (BN * B_ROW)    // 5120 words  (20480 B)
#define SMEM_BYTES (STAGES * (A_STAGE_W + B_STAGE_W) * 4)   // 184320

// ---------------- scratch: tf32(rne)-rounded, cin-permuted copies ----------
__device__ __align__(1024) float g_x_t[NPIX * CCIN];    // [pix][cin']
__device__ __align__(1024) float g_w_t[CCOUT * KTOT];   // [cout][k'] transposed

// ---------------- helpers ----------------
__device__ __forceinline__ uint32_t smem_u32(const void* p) {
    uint32_t a;
    asm("{ .reg .u64 t; cvta.to.shared.u64 t, %1; cvt.u32.u64 %0, t; }"
        : "=r"(a) : "l"(p));
    return a;
}

__device__ __forceinline__ void cp16(uint32_t dst, const void* src, uint32_t srcsz) {
    asm volatile("cp.async.cg.shared.global [%0], [%1], 16, %2;"
                 :: "r"(dst), "l"(src), "r"(srcsz) : "memory");
}
#define CP_COMMIT() asm volatile("cp.async.commit_group;" ::: "memory")
#define CP_WAIT1()  asm volatile("cp.async.wait_group 1;" ::: "memory")

__device__ __forceinline__ void mma_tf32(float c[4], const uint32_t a[4],
                                         const uint32_t b[2]) {
    asm volatile(
        "mma.sync.aligned.m16n8k8.row.col.f32.tf32.tf32.f32 "
        "{%0,%1,%2,%3}, {%4,%5,%6,%7}, {%8,%9}, {%0,%1,%2,%3};"
        : "+f"(c[0]), "+f"(c[1]), "+f"(c[2]), "+f"(c[3])
        : "r"(a[0]), "r"(a[1]), "r"(a[2]), "r"(a[3]),
          "r"(b[0]), "r"(b[1]));
}

__device__ __forceinline__ float rna_tf32(float v) {
    uint32_t r;
    asm("cvt.rna.tf32.f32 %0, %1;" : "=r"(r) : "f"(v));
    return __uint_as_float(r);
}

// ---------------- pre-kernels ----------------
// x: per 8-group of cin, output order (c0,c4,c1,c5,c2,c6,c3,c7), tf32(rne).
__global__ void k_prep_x(const float* __restrict__ in, float* __restrict__ outp) {
    const int g = blockIdx.x * blockDim.x + threadIdx.x;   // 8-group index
    const float4* i4 = (const float4*)(in) + g * 2;
    float4 a = i4[0];   // c0..c3
    float4 b = i4[1];   // c4..c7
    float4 o0, o1;
    o0.x = rna_tf32(a.x); o0.y = rna_tf32(b.x);
    o0.z = rna_tf32(a.y); o0.w = rna_tf32(b.y);
    o1.x = rna_tf32(a.z); o1.y = rna_tf32(b.z);
    o1.z = rna_tf32(a.w); o1.w = rna_tf32(b.w);
    float4* o4 = (float4*)(outp) + g * 2;
    o4[0] = o0;
    o4[1] = o1;
}

// w[k][cout] -> w_t[cout][k'] with same within-8 permutation, tf32(rne).
__global__ void k_prep_w(const float* __restrict__ w, float* __restrict__ wt) {
    const int idx = blockIdx.x * blockDim.x + threadIdx.x;  // [co][kp]
    const int co = idx / KTOT;
    const int kp = idx % KTOT;
    const int g = kp >> 3, r = kp & 7;
    const int c = (r & 1) ? (4 + (r >> 1)) : (r >> 1);      // inverse permutation
    wt[idx] = rna_tf32(w[(size_t)(g * 8 + c) * CCOUT + co]);
}

// ---------------- main kernel ----------------
__global__ __launch_bounds__(NTHREADS, 1)
void conv_mma(const float* __restrict__ xt, const float* __restrict__ wt,
              const float* __restrict__ bias, float* __restrict__ out)
{
    extern __shared__ float smem[];
    const uint32_t sm_a = smem_u32(smem);
    const uint32_t sm_b = sm_a + STAGES * A_STAGE_W * 4;

    const int tid  = threadIdx.x;
    const int wid  = tid >> 5;
    const int lane = tid & 31;
    const int lr   = lane >> 2;    // 0..7
    const int lc   = lane & 3;     // 0..3
    const int bn = blockIdx.x;     // 0..1
    const int bm = blockIdx.y;     // 0..391

    // ---- A loader coords: 8 pixels per thread ----
    const int s7 = tid & 7;        // 16B segment within 128B cin-chunk
    int ah[8], aw[8];
    uint32_t abase[8];
    #pragma unroll
    for (int q = 0; q < 8; ++q) {
        int pix = bm * BM + (tid >> 3) + q * 32;
        int n   = pix / (CH * CW);
        int hw  = pix % (CH * CW);
        ah[q] = hw / CW;
        aw[q] = hw % CW;
        abase[q] = (uint32_t)n * (CH * CW * CCIN);
    }

    // warp tile 64x64 -> 4 m-tiles x 8 n-tiles x 4 regs = 128 acc regs
    float acc[4][8][4];
    #pragma unroll
    for (int t = 0; t < 4; ++t)
        #pragma unroll
        for (int u = 0; u < 8; ++u)
            #pragma unroll
            for (int r = 0; r < 4; ++r)
                acc[t][u][r] = 0.0f;

    const int warp_m = wid >> 1;   // 0..3
    const int warp_n = wid & 1;    // 0..1

    // ---------------- load issuer ----------------
    auto load_chunk = [&](int i, int stage) {
        const int tap = i >> 2, csub = i & 3;
        const int dh = tap / 3 - 1, dw = tap % 3 - 1;
        const uint32_t a_st = sm_a + stage * A_STAGE_W * 4;
        const uint32_t b_st = sm_b + stage * B_STAGE_W * 4;
        #pragma unroll
        for (int q = 0; q < 8; ++q) {
            const int h2 = ah[q] + dh, w2 = aw[q] + dw;
            const bool ok = ((unsigned)h2 < CH) && ((unsigned)w2 < CW);
            const uint32_t off = ok
                ? (abase[q] + (uint32_t)(h2 * CW + w2) * CCIN + csub * 32 + s7 * 4)
                : 0u;
            const uint32_t dst = a_st
                + (uint32_t)((tid >> 3) + q * 32) * (A_ROW * 4) + s7 * 16;
            cp16(dst, xt + off, ok ? 16u : 0u);
        }
        // B: w_t[bn*128+row][tap*128 + csub*32 + seg*4], rows 0..127, 8 segs
        #pragma unroll
        for (int q = 0; q < 4; ++q) {
            const int f   = tid + q * 256;
            const int row = f >> 3;           // 0..127
            const int seg = f & 7;
            const float* src = wt + (size_t)(bn * BN + row) * KTOT
                             + tap * 128 + csub * 32 + seg * 4;
            cp16(b_st + (uint32_t)row * (B_ROW * 4) + seg * 16, src, 16u);
        }
        CP_COMMIT();
    };

    load_chunk(0, 0);
    load_chunk(1, 1);

    for (int i = 0; i < NCHUNKS; ++i) {
        CP_WAIT1();
        __syncthreads();

        if (i + 2 < NCHUNKS) load_chunk(i + 2, (i + 2) % STAGES);
        else CP_COMMIT();

        const int stage = i % STAGES;
        const float* As = smem + stage * A_STAGE_W + (warp_m * 64) * A_ROW;
        const float* Bs = smem + STAGES * A_STAGE_W + stage * B_STAGE_W
                        + (warp_n * 64) * B_ROW;

        #pragma unroll
        for (int j = 0; j < 4; ++j) {
            const int kc = j * 8 + lc * 2;   // permuted pair (orig lc, lc+4)
            uint32_t a[4][4], b[8][2];
            #pragma unroll
            for (int t = 0; t < 4; ++t) {
                const float2 lo = *(const float2*)(As + (t * 16 + lr) * A_ROW + kc);
                const float2 hi = *(const float2*)(As + (t * 16 + lr + 8) * A_ROW + kc);
                a[t][0] = __float_as_uint(lo.x);
                a[t][1] = __float_as_uint(hi.x);
                a[t][2] = __float_as_uint(lo.y);
                a[t][3] = __float_as_uint(hi.y);
            }
            #pragma unroll
            for (int u = 0; u < 8; ++u) {
                const float2 bb = *(const float2*)(Bs + (u * 8 + lr) * B_ROW + kc);
                b[u][0] = __float_as_uint(bb.x);
                b[u][1] = __float_as_uint(bb.y);
            }
            #pragma unroll
            for (int t = 0; t < 4; ++t)
                #pragma unroll
                for (int u = 0; u < 8; ++u)
                    mma_tf32(acc[t][u], a[t], b[u]);
        }
    }

    // ---------------- epilogue: bias + store ----------------
    float bv0[8], bv1[8];
    #pragma unroll
    for (int u = 0; u < 8; ++u) {
        const int c = bn * BN + warp_n * 64 + u * 8 + lc * 2;
        bv0[u] = bias[c];
        bv1[u] = bias[c + 1];
    }
    #pragma unroll
    for (int t = 0; t < 4; ++t) {
        const int r0 = bm * BM + warp_m * 64 + t * 16 + lr;
        #pragma unroll
        for (int u = 0; u < 8; ++u) {
            const int c = bn * BN + warp_n * 64 + u * 8 + lc * 2;
            float2 v0 = make_float2(acc[t][u][0] + bv0[u], acc[t][u][1] + bv1[u]);
            float2 v1 = make_float2(acc[t][u][2] + bv0[u], acc[t][u][3] + bv1[u]);
            *(float2*)(out + (size_t)r0 * CCOUT + c)       = v0;
            *(float2*)(out + (size_t)(r0 + 8) * CCOUT + c) = v1;
        }
    }
}

// ---------------- host launch ----------------
extern "C" void kernel_launch(void* const* d_in, const int* in_sizes, int n_in,
                              void* d_out, int out_size)
{
    const float* x    = (const float*)d_in[0];
    const float* w    = (const float*)d_in[1];
    const float* bias = (const float*)d_in[2];
    float* out = (float*)d_out;

    float *gx = nullptr, *gw = nullptr;
    cudaGetSymbolAddress((void**)&gx, g_x_t);
    cudaGetSymbolAddress((void**)&gw, g_w_t);

    // pre-passes: tf32(rne) + within-8 cin permutation (+ w transpose)
    k_prep_x<<<NPIX * CCIN / 8 / 256, 256>>>(x, gx);      // 6272 blocks
    k_prep_w<<<KTOT * CCOUT / 256, 256>>>(w, gw);         // 1152 blocks

    cudaFuncSetAttribute(conv_mma, cudaFuncAttributeMaxDynamicSharedMemorySize,
                         SMEM_BYTES);
    dim3 grid(CCOUT / BN, NPIX / BM);   // (2, 392)
    conv_mma<<<grid, NTHREADS, SMEM_BYTES>>>(gx, gw, bias, out);
}

// round 7
// speedup vs baseline: 2.9847x; 1.0667x over previous
#include <cuda_runtime.h>
#include <cstdint>

// SAME-padded stride-1 3x3 conv, NHWC fp32, tf32 mma.sync implicit GEMM.
// Round 7: halo-tile A (loaded once per cin-chunk, 9x fewer LDGSTS),
// CTA = 8 rows x 56 cols of one image (BM=448) x BN=64 couts.
// 14 warps (7m x 2n, warp 64x32).

#define CB    32
#define CH    56
#define CW    56
#define CCIN  128
#define CCOUT 256
#define NPIX  (CB * CH * CW)      // 100352
#define KTOT  1152
#define NPHASES 36                // 4 cin-chunks * 9 taps

#define BM 448                    // 8 rows x 56
#define BN 64
#define NTHREADS 448              // 14 warps

#define HR 10                     // halo rows  (8 + 2)
#define HC 58                     // halo cols  (56 + 2)
#define HPIX (HR * HC)            // 580
#define AROW 40                   // words per halo pixel (32 data + 8 pad)
#define BROW 40
#define A_STAGE_W (HPIX * AROW)   // 23200 words (92800 B)
#define B_STAGE_W (BN * BROW)     // 2560 words  (10240 B)
#define SMEM_BYTES ((2 * A_STAGE_W + 2 * B_STAGE_W) * 4)   // 206080

// ---------------- scratch: tf32(rne)-rounded, cin-permuted copies ----------
__device__ __align__(1024) float g_x_t[NPIX * CCIN];    // [pix][cin']
__device__ __align__(1024) float g_w_t[CCOUT * KTOT];   // [cout][k'] transposed

// ---------------- helpers ----------------
__device__ __forceinline__ uint32_t smem_u32(const void* p) {
    uint32_t a;
    asm("{ .reg .u64 t; cvta.to.shared.u64 t, %1; cvt.u32.u64 %0, t; }"
        : "=r"(a) : "l"(p));
    return a;
}

__device__ __forceinline__ void cp16(uint32_t dst, const void* src, uint32_t srcsz) {
    asm volatile("cp.async.cg.shared.global [%0], [%1], 16, %2;"
                 :: "r"(dst), "l"(src), "r"(srcsz) : "memory");
}
#define CP_COMMIT() asm volatile("cp.async.commit_group;" ::: "memory")
#define CP_WAIT0()  asm volatile("cp.async.wait_group 0;" ::: "memory")

__device__ __forceinline__ void mma_tf32(float c[4], const uint32_t a[4],
                                         const uint32_t b[2]) {
    asm volatile(
        "mma.sync.aligned.m16n8k8.row.col.f32.tf32.tf32.f32 "
        "{%0,%1,%2,%3}, {%4,%5,%6,%7}, {%8,%9}, {%0,%1,%2,%3};"
        : "+f"(c[0]), "+f"(c[1]), "+f"(c[2]), "+f"(c[3])
        : "r"(a[0]), "r"(a[1]), "r"(a[2]), "r"(a[3]),
          "r"(b[0]), "r"(b[1]));
}

__device__ __forceinline__ float rna_tf32(float v) {
    uint32_t r;
    asm("cvt.rna.tf32.f32 %0, %1;" : "=r"(r) : "f"(v));
    return __uint_as_float(r);
}

// ---------------- pre-kernels ----------------
// x: per 8-group of cin, output order (c0,c4,c1,c5,c2,c6,c3,c7), tf32(rne).
__global__ void k_prep_x(const float* __restrict__ in, float* __restrict__ outp) {
    const int g = blockIdx.x * blockDim.x + threadIdx.x;   // 8-group index
    const float4* i4 = (const float4*)(in) + g * 2;
    float4 a = i4[0];   // c0..c3
    float4 b = i4[1];   // c4..c7
    float4 o0, o1;
    o0.x = rna_tf32(a.x); o0.y = rna_tf32(b.x);
    o0.z = rna_tf32(a.y); o0.w = rna_tf32(b.y);
    o1.x = rna_tf32(a.z); o1.y = rna_tf32(b.z);
    o1.z = rna_tf32(a.w); o1.w = rna_tf32(b.w);
    float4* o4 = (float4*)(outp) + g * 2;
    o4[0] = o0;
    o4[1] = o1;
}

// w[k][cout] -> w_t[cout][k'] with same within-8 permutation, tf32(rne).
__global__ void k_prep_w(const float* __restrict__ w, float* __restrict__ wt) {
    const int idx = blockIdx.x * blockDim.x + threadIdx.x;  // [co][kp]
    const int co = idx / KTOT;
    const int kp = idx % KTOT;
    const int g = kp >> 3, r = kp & 7;
    const int c = (r & 1) ? (4 + (r >> 1)) : (r >> 1);      // inverse permutation
    wt[idx] = rna_tf32(w[(size_t)(g * 8 + c) * CCOUT + co]);
}

// ---------------- main kernel ----------------
__global__ __launch_bounds__(NTHREADS, 1)
void conv_mma(const float* __restrict__ xt, const float* __restrict__ wt,
              const float* __restrict__ bias, float* __restrict__ out)
{
    extern __shared__ float smem[];
    const uint32_t sbase = smem_u32(smem);

    const int tid  = threadIdx.x;
    const int wid  = tid >> 5;
    const int lane = tid & 31;
    const int lr   = lane >> 2;    // 0..7
    const int lc   = lane & 3;     // 0..3
    const int bn = blockIdx.x;     // 0..3   (cout block of 64)
    const int n  = blockIdx.y / 7;           // image
    const int h0 = (blockIdx.y % 7) * 8;     // first output row

    const int warp_m = wid >> 1;   // 0..6
    const int warp_n = wid & 1;    // 0..1

    // ---- fragment A base offsets in the halo tile (words) ----
    int abase[4][2];
    #pragma unroll
    for (int t = 0; t < 4; ++t)
        #pragma unroll
        for (int h = 0; h < 2; ++h) {
            const int m = warp_m * 64 + t * 16 + lr + h * 8;   // 0..447
            const int r = m / 56, c = m % 56;
            abase[t][h] = ((r + 1) * HC + (c + 1)) * AROW;
        }

    const float* xbase = xt + (size_t)(n * (CH * CW)) * CCIN;

    float acc[4][4][4];
    #pragma unroll
    for (int t = 0; t < 4; ++t)
        #pragma unroll
        for (int u = 0; u < 4; ++u)
            #pragma unroll
            for (int r = 0; r < 4; ++r)
                acc[t][u][r] = 0.0f;

    // ---- fill 2 halo rows (rq = 0..4) of A buffer `buf` for `chunk` ----
    auto fill_A_rows = [&](int chunk, int buf, int rq) {
        const uint32_t dst0 = sbase + (uint32_t)buf * (A_STAGE_W * 4);
        for (int idx = tid; idx < 2 * HC * 8; idx += NTHREADS) {
            const int pix = rq * (2 * HC) + (idx >> 3);
            const int seg = idx & 7;
            const int hr = pix / HC, wc = pix % HC;
            const int h = h0 - 1 + hr, w2 = wc - 1;
            const bool ok = ((unsigned)h < CH) && ((unsigned)w2 < CW);
            const float* src = xbase
                + (ok ? ((size_t)(h * CW + w2) * CCIN + chunk * 32 + seg * 4) : 0);
            cp16(dst0 + (uint32_t)pix * (AROW * 4) + seg * 16, src, ok ? 16u : 0u);
        }
    };
    // ---- fill B buffer `buf` with weights for (tap, chunk) ----
    auto fill_B = [&](int tap, int chunk, int buf) {
        const uint32_t dst0 = sbase + (uint32_t)(2 * A_STAGE_W + buf * B_STAGE_W) * 4;
        for (int idx = tid; idx < BN * 8; idx += NTHREADS) {
            const int row = idx >> 3, seg = idx & 7;
            const float* src = wt + (size_t)(bn * BN + row) * KTOT
                             + tap * 128 + chunk * 32 + seg * 4;
            cp16(dst0 + (uint32_t)row * (BROW * 4) + seg * 16, src, 16u);
        }
    };

    // ---- prologue: A(chunk0) full + B(phase0) ----
    #pragma unroll
    for (int rq = 0; rq < 5; ++rq) fill_A_rows(0, 0, rq);
    fill_B(0, 0, 0);
    CP_COMMIT();

    #pragma unroll 1
    for (int p = 0; p < NPHASES; ++p) {
        CP_WAIT0();
        __syncthreads();

        const int chunk = p / 9;
        const int tap   = p - chunk * 9;

        // issue next-phase loads (land by next phase's wait)
        if (p + 1 < NPHASES) fill_B((p + 1 == 9 * (chunk + 1)) ? 0 : tap + 1,
                                    (p + 1) / 9, (p + 1) & 1);
        if (chunk < 3 && tap >= 2 && tap <= 6)
            fill_A_rows(chunk + 1, (chunk + 1) & 1, tap - 2);
        CP_COMMIT();

        const float* As = smem + (chunk & 1) * A_STAGE_W;
        const float* Bs = smem + 2 * A_STAGE_W + (p & 1) * B_STAGE_W
                        + (warp_n * 32) * BROW;
        const int kh = tap / 3, kw = tap - kh * 3;
        const int toff = ((kh - 1) * HC + (kw - 1)) * AROW;

        #pragma unroll
        for (int j = 0; j < 4; ++j) {
            const int kc = j * 8 + lc * 2;   // permuted pair (orig lc, lc+4)
            uint32_t a[4][4], b[4][2];
            #pragma unroll
            for (int t = 0; t < 4; ++t) {
                const float2 lo = *(const float2*)(As + abase[t][0] + toff + kc);
                const float2 hi = *(const float2*)(As + abase[t][1] + toff + kc);
                a[t][0] = __float_as_uint(lo.x);
                a[t][1] = __float_as_uint(hi.x);
                a[t][2] = __float_as_uint(lo.y);
                a[t][3] = __float_as_uint(hi.y);
            }
            #pragma unroll
            for (int u = 0; u < 4; ++u) {
                const float2 bb = *(const float2*)(Bs + (u * 8 + lr) * BROW + kc);
                b[u][0] = __float_as_uint(bb.x);
                b[u][1] = __float_as_uint(bb.y);
            }
            #pragma unroll
            for (int t = 0; t < 4; ++t)
                #pragma unroll
                for (int u = 0; u < 4; ++u)
                    mma_tf32(acc[t][u], a[t], b[u]);
        }
    }

    // ---------------- epilogue: bias + store ----------------
    const int pixbase = n * (CH * CW) + h0 * CW;
    float bv0[4], bv1[4];
    #pragma unroll
    for (int u = 0; u < 4; ++u) {
        const int c = bn * BN + warp_n * 32 + u * 8 + lc * 2;
        bv0[u] = bias[c];
        bv1[u] = bias[c + 1];
    }
    #pragma unroll
    for (int t = 0; t < 4; ++t) {
        const int m0 = warp_m * 64 + t * 16 + lr;
        #pragma unroll
        for (int u = 0; u < 4; ++u) {
            const int c = bn * BN + warp_n * 32 + u * 8 + lc * 2;
            float2 v0 = make_float2(acc[t][u][0] + bv0[u], acc[t][u][1] + bv1[u]);
            float2 v1 = make_float2(acc[t][u][2] + bv0[u], acc[t][u][3] + bv1[u]);
            *(float2*)(out + (size_t)(pixbase + m0) * CCOUT + c)     = v0;
            *(float2*)(out + (size_t)(pixbase + m0 + 8) * CCOUT + c) = v1;
        }
    }
}

// ---------------- host launch ----------------
extern "C" void kernel_launch(void* const* d_in, const int* in_sizes, int n_in,
                              void* d_out, int out_size)
{
    const float* x    = (const float*)d_in[0];
    const float* w    = (const float*)d_in[1];
    const float* bias = (const float*)d_in[2];
    float* out = (float*)d_out;

    float *gx = nullptr, *gw = nullptr;
    cudaGetSymbolAddress((void**)&gx, g_x_t);
    cudaGetSymbolAddress((void**)&gw, g_w_t);

    // pre-passes: tf32(rne) + within-8 cin permutation (+ w transpose)
    k_prep_x<<<NPIX * CCIN / 8 / 256, 256>>>(x, gx);      // 6272 blocks
    k_prep_w<<<KTOT * CCOUT / 256, 256>>>(w, gw);         // 1152 blocks

    cudaFuncSetAttribute(conv_mma, cudaFuncAttributeMaxDynamicSharedMemorySize,
                         SMEM_BYTES);
    // grid: 4 cout-blocks x (32 images * 7 row-blocks) = 896 CTAs
    dim3 grid(CCOUT / BN, CB * (CH / 8));
    conv_mma<<<grid, NTHREADS, SMEM_BYTES>>>(gx, gw, bias, out);
}

// round 8
// speedup vs baseline: 3.0810x; 1.0323x over previous
#include <cuda_runtime.h>
#include <cstdint>

// SAME-padded stride-1 3x3 conv, NHWC fp32, tf32 mma.sync implicit GEMM.
// Round 8: 2 taps per phase (20 phases, was 36), split cp.async commit
// groups with wait_group 1, merged prep kernel.
// CTA = 8 rows x 56 cols of one image (BM=448) x BN=64 couts, 14 warps.

#define CB    32
#define CH    56
#define CW    56
#define CCIN  128
#define CCOUT 256
#define NPIX  (CB * CH * CW)      // 100352
#define KTOT  1152
#define NPHASES 20                // 4 cin-chunks * 5 phases (2,2,2,2,1 taps)

#define BM 448                    // 8 rows x 56
#define BN 64
#define NTHREADS 448              // 14 warps, 7(M) x 2(N), warp 64x32

#define HR 10                     // halo rows  (8 + 2)
#define HC 58                     // halo cols  (56 + 2)
#define HPIX (HR * HC)            // 580
#define AROW 40                   // words per halo pixel (32 data + 8 pad)
#define BROW 40
#define A_STAGE_W (HPIX * AROW)   // 23200 words (92800 B)
#define B_TAP_W   (BN * BROW)     // 2560 words  (10240 B)
#define B_STAGE_W (2 * B_TAP_W)   // 5120 words  (2 taps)
#define SMEM_BYTES ((2 * A_STAGE_W + 2 * B_STAGE_W) * 4)   // 226560

#define XGROUPS (NPIX * CCIN / 8 / 256)   // 6272 blocks for x-prep

// ---------------- scratch: tf32(rne)-rounded, cin-permuted copies ----------
__device__ __align__(1024) float g_x_t[NPIX * CCIN];    // [pix][cin']
__device__ __align__(1024) float g_w_t[CCOUT * KTOT];   // [cout][k'] transposed

// ---------------- helpers ----------------
__device__ __forceinline__ uint32_t smem_u32(const void* p) {
    uint32_t a;
    asm("{ .reg .u64 t; cvta.to.shared.u64 t, %1; cvt.u32.u64 %0, t; }"
        : "=r"(a) : "l"(p));
    return a;
}

__device__ __forceinline__ void cp16(uint32_t dst, const void* src, uint32_t srcsz) {
    asm volatile("cp.async.cg.shared.global [%0], [%1], 16, %2;"
                 :: "r"(dst), "l"(src), "r"(srcsz) : "memory");
}
#define CP_COMMIT() asm volatile("cp.async.commit_group;" ::: "memory")
#define CP_WAIT0()  asm volatile("cp.async.wait_group 0;" ::: "memory")
#define CP_WAIT1()  asm volatile("cp.async.wait_group 1;" ::: "memory")

__device__ __forceinline__ void mma_tf32(float c[4], const uint32_t a[4],
                                         const uint32_t b[2]) {
    asm volatile(
        "mma.sync.aligned.m16n8k8.row.col.f32.tf32.tf32.f32 "
        "{%0,%1,%2,%3}, {%4,%5,%6,%7}, {%8,%9}, {%0,%1,%2,%3};"
        : "+f"(c[0]), "+f"(c[1]), "+f"(c[2]), "+f"(c[3])
        : "r"(a[0]), "r"(a[1]), "r"(a[2]), "r"(a[3]),
          "r"(b[0]), "r"(b[1]));
}

__device__ __forceinline__ float rna_tf32(float v) {
    uint32_t r;
    asm("cvt.rna.tf32.f32 %0, %1;" : "=r"(r) : "f"(v));
    return __uint_as_float(r);
}

// ---------------- merged pre-kernel ----------------
// blocks [0, XGROUPS): x path — per 8-group of cin, output order
//   (c0,c4,c1,c5,c2,c6,c3,c7), tf32(rne), layout unchanged otherwise.
// blocks [XGROUPS, ...): w path — w[k][cout] -> w_t[cout][k'] with the
//   same within-8 permutation, tf32(rne).
__global__ void k_prep(const float* __restrict__ x, const float* __restrict__ w,
                       float* __restrict__ gx, float* __restrict__ gw)
{
    const int bid = blockIdx.x;
    if (bid < XGROUPS) {
        const int g = bid * 256 + threadIdx.x;
        const float4* i4 = (const float4*)(x) + g * 2;
        float4 a = i4[0];   // c0..c3
        float4 b = i4[1];   // c4..c7
        float4 o0, o1;
        o0.x = rna_tf32(a.x); o0.y = rna_tf32(b.x);
        o0.z = rna_tf32(a.y); o0.w = rna_tf32(b.y);
        o1.x = rna_tf32(a.z); o1.y = rna_tf32(b.z);
        o1.z = rna_tf32(a.w); o1.w = rna_tf32(b.w);
        float4* o4 = (float4*)(gx) + g * 2;
        o4[0] = o0;
        o4[1] = o1;
    } else {
        const int idx = (bid - XGROUPS) * 256 + threadIdx.x;  // [co][kp]
        const int co = idx / KTOT;
        const int kp = idx % KTOT;
        const int g = kp >> 3, r = kp & 7;
        const int c = (r & 1) ? (4 + (r >> 1)) : (r >> 1);    // inverse perm
        gw[idx] = rna_tf32(w[(size_t)(g * 8 + c) * CCOUT + co]);
    }
}

// ---------------- main kernel ----------------
__global__ __launch_bounds__(NTHREADS, 1)
void conv_mma(const float* __restrict__ xt, const float* __restrict__ wt,
              const float* __restrict__ bias, float* __restrict__ out)
{
    extern __shared__ float smem[];
    const uint32_t sbase = smem_u32(smem);

    const int tid  = threadIdx.x;
    const int wid  = tid >> 5;
    const int lane = tid & 31;
    const int lr   = lane >> 2;    // 0..7
    const int lc   = lane & 3;     // 0..3
    const int bn = blockIdx.x;     // 0..3   (cout block of 64)
    const int n  = blockIdx.y / 7;           // image
    const int h0 = (blockIdx.y % 7) * 8;     // first output row

    const int warp_m = wid >> 1;   // 0..6
    const int warp_n = wid & 1;    // 0..1

    // ---- fragment A base offsets in the halo tile (words) ----
    int abase[4][2];
    #pragma unroll
    for (int t = 0; t < 4; ++t)
        #pragma unroll
        for (int h = 0; h < 2; ++h) {
            const int m = warp_m * 64 + t * 16 + lr + h * 8;   // 0..447
            const int r = m / 56, c = m % 56;
            abase[t][h] = ((r + 1) * HC + (c + 1)) * AROW;
        }

    const float* xbase = xt + (size_t)(n * (CH * CW)) * CCIN;

    float acc[4][4][4];
    #pragma unroll
    for (int t = 0; t < 4; ++t)
        #pragma unroll
        for (int u = 0; u < 4; ++u)
            #pragma unroll
            for (int r = 0; r < 4; ++r)
                acc[t][u][r] = 0.0f;

    // ---- fill 2 halo rows (rq = 0..4) of A buffer `buf` for `chunk` ----
    auto fill_A_rows = [&](int chunk, int buf, int rq) {
        const uint32_t dst0 = sbase + (uint32_t)buf * (A_STAGE_W * 4);
        for (int idx = tid; idx < 2 * HC * 8; idx += NTHREADS) {
            const int pix = rq * (2 * HC) + (idx >> 3);
            const int seg = idx & 7;
            const int hr = pix / HC, wc = pix % HC;
            const int h = h0 - 1 + hr, w2 = wc - 1;
            const bool ok = ((unsigned)h < CH) && ((unsigned)w2 < CW);
            const float* src = xbase
                + (ok ? ((size_t)(h * CW + w2) * CCIN + chunk * 32 + seg * 4) : 0);
            cp16(dst0 + (uint32_t)pix * (AROW * 4) + seg * 16, src, ok ? 16u : 0u);
        }
    };
    // ---- fill B buffer for phase p: ntaps taps starting at t0, chunk ----
    auto fill_B = [&](int p) {
        const int q = p % 5, chunk = p / 5;
        const int t0 = 2 * q;
        const int ntaps = (q == 4) ? 1 : 2;
        const uint32_t dst0 = sbase
            + (uint32_t)(2 * A_STAGE_W + (p & 1) * B_STAGE_W) * 4;
        for (int idx = tid; idx < ntaps * BN * 8; idx += NTHREADS) {
            const int tt  = idx >> 9;         // 0..1
            const int row = (idx >> 3) & 63;
            const int seg = idx & 7;
            const float* src = wt + (size_t)(bn * BN + row) * KTOT
                             + (t0 + tt) * 128 + chunk * 32 + seg * 4;
            cp16(dst0 + (uint32_t)(tt * BN + row) * (BROW * 4) + seg * 16,
                 src, 16u);
        }
    };

    // ---- prologue: A(chunk0) full + B(phase0), one group ----
    #pragma unroll
    for (int rq = 0; rq < 5; ++rq) fill_A_rows(0, 0, rq);
    fill_B(0);
    CP_COMMIT();

    #pragma unroll 1
    for (int p = 0; p < NPHASES; ++p) {
        const int q = p % 5, chunk = p / 5;
        const int t0 = 2 * q;
        const int ntaps = (q == 4) ? 1 : 2;

        // chunk-boundary phases need the freshest A-refill group too
        if (q == 0) CP_WAIT0();
        else        CP_WAIT1();
        __syncthreads();

        // next-phase B fills (own group), then A refill rows (own group,
        // allowed to stay outstanding through the next wait)
        if (p + 1 < NPHASES) fill_B(p + 1);
        CP_COMMIT();
        if (chunk < 3) fill_A_rows(chunk + 1, (chunk + 1) & 1, q);
        CP_COMMIT();

        const float* As = smem + (chunk & 1) * A_STAGE_W;

        #pragma unroll
        for (int tt = 0; tt < 2; ++tt) {
            if (tt < ntaps) {
                const int tap = t0 + tt;
                const int kh = tap / 3, kw = tap - kh * 3;
                const int toff = ((kh - 1) * HC + (kw - 1)) * AROW;
                const float* Bs = smem + 2 * A_STAGE_W + (p & 1) * B_STAGE_W
                                + tt * B_TAP_W + (warp_n * 32) * BROW;

                #pragma unroll
                for (int j = 0; j < 4; ++j) {
                    const int kc = j * 8 + lc * 2;  // permuted pair (lc, lc+4)
                    uint32_t a[4][4], b[4][2];
                    #pragma unroll
                    for (int t = 0; t < 4; ++t) {
                        const float2 lo =
                            *(const float2*)(As + abase[t][0] + toff + kc);
                        const float2 hi =
                            *(const float2*)(As + abase[t][1] + toff + kc);
                        a[t][0] = __float_as_uint(lo.x);
                        a[t][1] = __float_as_uint(hi.x);
                        a[t][2] = __float_as_uint(lo.y);
                        a[t][3] = __float_as_uint(hi.y);
                    }
                    #pragma unroll
                    for (int u = 0; u < 4; ++u) {
                        const float2 bb =
                            *(const float2*)(Bs + (u * 8 + lr) * BROW + kc);
                        b[u][0] = __float_as_uint(bb.x);
                        b[u][1] = __float_as_uint(bb.y);
                    }
                    #pragma unroll
                    for (int t = 0; t < 4; ++t)
                        #pragma unroll
                        for (int u = 0; u < 4; ++u)
                            mma_tf32(acc[t][u], a[t], b[u]);
                }
            }
        }
    }

    // ---------------- epilogue: bias + store ----------------
    const int pixbase = n * (CH * CW) + h0 * CW;
    float bv0[4], bv1[4];
    #pragma unroll
    for (int u = 0; u < 4; ++u) {
        const int c = bn * BN + warp_n * 32 + u * 8 + lc * 2;
        bv0[u] = bias[c];
        bv1[u] = bias[c + 1];
    }
    #pragma unroll
    for (int t = 0; t < 4; ++t) {
        const int m0 = warp_m * 64 + t * 16 + lr;
        #pragma unroll
        for (int u = 0; u < 4; ++u) {
            const int c = bn * BN + warp_n * 32 + u * 8 + lc * 2;
            float2 v0 = make_float2(acc[t][u][0] + bv0[u], acc[t][u][1] + bv1[u]);
            float2 v1 = make_float2(acc[t][u][2] + bv0[u], acc[t][u][3] + bv1[u]);
            *(float2*)(out + (size_t)(pixbase + m0) * CCOUT + c)     = v0;
            *(float2*)(out + (size_t)(pixbase + m0 + 8) * CCOUT + c) = v1;
        }
    }
}

// ---------------- host launch ----------------
extern "C" void kernel_launch(void* const* d_in, const int* in_sizes, int n_in,
                              void* d_out, int out_size)
{
    const float* x    = (const float*)d_in[0];
    const float* w    = (const float*)d_in[1];
    const float* bias = (const float*)d_in[2];
    float* out = (float*)d_out;

    float *gx = nullptr, *gw = nullptr;
    cudaGetSymbolAddress((void**)&gx, g_x_t);
    cudaGetSymbolAddress((void**)&gw, g_w_t);

    // merged pre-pass: tf32(rne) + within-8 cin permutation (+ w transpose)
    k_prep<<<XGROUPS + KTOT * CCOUT / 256, 256>>>(x, w, gx, gw);

    cudaFuncSetAttribute(conv_mma, cudaFuncAttributeMaxDynamicSharedMemorySize,
                         SMEM_BYTES);
    // grid: 4 cout-blocks x (32 images * 7 row-blocks) = 896 CTAs
    dim3 grid(CCOUT / BN, CB * (CH / 8));
    conv_mma<<<grid, NTHREADS, SMEM_BYTES>>>(gx, gw, bias, out);
}